// round 14
// baseline (speedup 1.0000x reference)
#include <cuda_runtime.h>

#define N_TOK  4096
#define HEADS  4
#define DHEAD  32
#define BATCH  2
#define CDIM   256
#define SCALE  0.17677669529663687f   // 1/sqrt(32)

// Scratch (device globals -- no allocations allowed)
__device__ float g_q [BATCH*HEADS*DHEAD*N_TOK];   // [b][h][d][n]
__device__ float g_k [BATCH*HEADS*DHEAD*N_TOK];   // [b][h][d][n]
__device__ float g_v [BATCH*HEADS*N_TOK*DHEAD];   // [b][h][n][d]
__device__ float g_ao[BATCH*HEADS*N_TOK*DHEAD];   // [b][h][n][d]

// ---------------------------------------------------------------------------
// Kernel 1: QKV projection.  C[o][i] = sum_c W[o][c] * X[c][i]
// M=384 (o), N=4096 (i), K=256, per batch. 64x64 tile, 4x4 micro, 256 thr.
// q (scaled) and k written d-major; v written token-major.
// ---------------------------------------------------------------------------
__global__ __launch_bounds__(256) void qkv_kernel(const float* __restrict__ x,
                                                  const float* __restrict__ w) {
    const int b  = blockIdx.z;
    const int m0 = blockIdx.y * 64;
    const int n0 = blockIdx.x * 64;
    __shared__ float Ws[16][68];
    __shared__ float Xs[16][68];
    const int t = threadIdx.x, tx = t & 15, ty = t >> 4;
    float acc[4][4] = {};
    const float* xb = x + (size_t)b * CDIM * N_TOK;

    for (int kk = 0; kk < CDIM; kk += 16) {
#pragma unroll
        for (int r = 0; r < 4; r++) {
            int idx = r * 256 + t;
            int m = idx >> 4, k = idx & 15;
            Ws[k][m] = w[(m0 + m) * CDIM + kk + k];
            int k2 = idx >> 6, n = idx & 63;
            Xs[k2][n] = xb[(kk + k2) * N_TOK + n0 + n];
        }
        __syncthreads();
#pragma unroll
        for (int k = 0; k < 16; k++) {
            float4 w4 = *(const float4*)&Ws[k][ty * 4];
            float4 x4 = *(const float4*)&Xs[k][tx * 4];
            float wa[4] = {w4.x, w4.y, w4.z, w4.w};
            float xa[4] = {x4.x, x4.y, x4.z, x4.w};
#pragma unroll
            for (int mi = 0; mi < 4; mi++)
#pragma unroll
                for (int ni = 0; ni < 4; ni++)
                    acc[mi][ni] = fmaf(wa[mi], xa[ni], acc[mi][ni]);
        }
        __syncthreads();
    }

#pragma unroll
    for (int mi = 0; mi < 4; mi++) {
        const int o  = m0 + ty * 4 + mi;
        const int g  = o >> 7;          // 0=q 1=k 2=v
        const int r7 = o & 127;
        const int h  = r7 >> 5, d = r7 & 31;
        const int n  = n0 + tx * 4;
        if (g == 0) {
            float4 v = make_float4(acc[mi][0] * SCALE, acc[mi][1] * SCALE,
                                   acc[mi][2] * SCALE, acc[mi][3] * SCALE);
            *(float4*)&g_q[(((b * HEADS + h) * DHEAD + d) * N_TOK) + n] = v;
        } else if (g == 1) {
            float4 v = make_float4(acc[mi][0], acc[mi][1], acc[mi][2], acc[mi][3]);
            *(float4*)&g_k[(((b * HEADS + h) * DHEAD + d) * N_TOK) + n] = v;
        } else {
#pragma unroll
            for (int ni = 0; ni < 4; ni++)
                g_v[(((b * HEADS + h) * N_TOK) + n + ni) * DHEAD + d] = acc[mi][ni];
        }
    }
}

// ---------------------------------------------------------------------------
// Kernel 2: flash attention, fp32, online softmax.
// Grid (n/64, heads, batch), 256 threads.
// S-phase: 16x16 thread grid, 4x4 micro over (i,j).  Row reductions via shfl
// (each row's 16 threads are 16 contiguous lanes of one warp).
// PV-phase: remapped 32x8 thread grid: 2 rows x 4 d (float4 over d).
// ---------------------------------------------------------------------------
__global__ __launch_bounds__(256) void attn_kernel() {
    const int b = blockIdx.z, h = blockIdx.y, it = blockIdx.x;
    const int bh = b * HEADS + h;
    const float* qb = g_q + (size_t)bh * DHEAD * N_TOK;
    const float* kb = g_k + (size_t)bh * DHEAD * N_TOK;
    const float* vb = g_v + (size_t)bh * N_TOK * DHEAD;
    float* aob = g_ao + (size_t)bh * N_TOK * DHEAD;
    const int i0 = it * 64;

    __shared__ float QsT[32][68];
    __shared__ float KsT[32][68];
    __shared__ float Vs [64][36];
    __shared__ float Ps [64][68];
    __shared__ float m_s[64], l_s[64], scale_s[64];

    const int t  = threadIdx.x;
    const int tx = t & 15, ty = t >> 4;     // S mapping
    const int d4 = t & 7,  irow = t >> 3;   // PV mapping

    // Load Q tile (transposed layout already: [d][n])
#pragma unroll
    for (int r = 0; r < 2; r++) {
        int idx = r * 256 + t;
        int d = idx >> 4, c = idx & 15;
        *(float4*)&QsT[d][c * 4] = *(const float4*)&qb[d * N_TOK + i0 + c * 4];
    }
    if (t < 64) { m_s[t] = -1e30f; l_s[t] = 0.f; }

    float o0[4] = {}, o1[4] = {};   // O accum: rows irow*2, irow*2+1; d = d4*4..+3

    for (int jt = 0; jt < 64; jt++) {
        const int j0 = jt * 64;
#pragma unroll
        for (int r = 0; r < 2; r++) {
            int idx = r * 256 + t;
            int d = idx >> 4, c = idx & 15;
            *(float4*)&KsT[d][c * 4] = *(const float4*)&kb[d * N_TOK + j0 + c * 4];
            int j = idx >> 3, c2 = idx & 7;
            *(float4*)&Vs[j][c2 * 4] = *(const float4*)&vb[(j0 + j) * DHEAD + c2 * 4];
        }
        __syncthreads();

        // S = Q K^T  (64x64, each thread 4x4)
        float acc[4][4] = {};
#pragma unroll
        for (int d = 0; d < 32; d++) {
            float4 q4 = *(const float4*)&QsT[d][ty * 4];
            float4 k4 = *(const float4*)&KsT[d][tx * 4];
            float qa[4] = {q4.x, q4.y, q4.z, q4.w};
            float ka[4] = {k4.x, k4.y, k4.z, k4.w};
#pragma unroll
            for (int mi = 0; mi < 4; mi++)
#pragma unroll
                for (int ji = 0; ji < 4; ji++)
                    acc[mi][ji] = fmaf(qa[mi], ka[ji], acc[mi][ji]);
        }

        // Online softmax per row
#pragma unroll
        for (int mi = 0; mi < 4; mi++) {
            const int i = ty * 4 + mi;
            float rmax = fmaxf(fmaxf(acc[mi][0], acc[mi][1]),
                               fmaxf(acc[mi][2], acc[mi][3]));
#pragma unroll
            for (int msk = 8; msk >= 1; msk >>= 1)
                rmax = fmaxf(rmax, __shfl_xor_sync(0xffffffffu, rmax, msk));
            const float mold = m_s[i];
            const float mnew = fmaxf(mold, rmax);
            float p0 = __expf(acc[mi][0] - mnew);
            float p1 = __expf(acc[mi][1] - mnew);
            float p2 = __expf(acc[mi][2] - mnew);
            float p3 = __expf(acc[mi][3] - mnew);
            float rsum = (p0 + p1) + (p2 + p3);
#pragma unroll
            for (int msk = 8; msk >= 1; msk >>= 1)
                rsum += __shfl_xor_sync(0xffffffffu, rsum, msk);
            *(float4*)&Ps[i][tx * 4] = make_float4(p0, p1, p2, p3);
            if (tx == 0) {
                const float sc = __expf(mold - mnew);
                m_s[i] = mnew;
                scale_s[i] = sc;
                l_s[i] = l_s[i] * sc + rsum;
            }
        }
        __syncthreads();

        // O = O*scale + P @ V
        const float sc0 = scale_s[irow * 2];
        const float sc1 = scale_s[irow * 2 + 1];
#pragma unroll
        for (int c = 0; c < 4; c++) { o0[c] *= sc0; o1[c] *= sc1; }
#pragma unroll
        for (int j = 0; j < 64; j++) {
            float4 v4 = *(const float4*)&Vs[j][d4 * 4];
            float p0 = Ps[irow * 2][j];
            float p1 = Ps[irow * 2 + 1][j];
            o0[0] = fmaf(p0, v4.x, o0[0]);
            o0[1] = fmaf(p0, v4.y, o0[1]);
            o0[2] = fmaf(p0, v4.z, o0[2]);
            o0[3] = fmaf(p0, v4.w, o0[3]);
            o1[0] = fmaf(p1, v4.x, o1[0]);
            o1[1] = fmaf(p1, v4.y, o1[1]);
            o1[2] = fmaf(p1, v4.z, o1[2]);
            o1[3] = fmaf(p1, v4.w, o1[3]);
        }
        __syncthreads();
    }

    const float inv0 = 1.0f / l_s[irow * 2];
    const float inv1 = 1.0f / l_s[irow * 2 + 1];
    float4 r0 = make_float4(o0[0] * inv0, o0[1] * inv0, o0[2] * inv0, o0[3] * inv0);
    float4 r1 = make_float4(o1[0] * inv1, o1[1] * inv1, o1[2] * inv1, o1[3] * inv1);
    *(float4*)&aob[(i0 + irow * 2)     * DHEAD + d4 * 4] = r0;
    *(float4*)&aob[(i0 + irow * 2 + 1) * DHEAD + d4 * 4] = r1;
}

// ---------------------------------------------------------------------------
// Kernel 3: output projection.  y[o][i] = bias[o] + sum_c w[o][c] * ao(c,i)
// M=256, N=4096, K=128 per batch. ao channel c = (h= c>>5, d = c&31).
// ---------------------------------------------------------------------------
__global__ __launch_bounds__(256) void proj_kernel(const float* __restrict__ w,
                                                   const float* __restrict__ bias,
                                                   float* __restrict__ y) {
    const int b  = blockIdx.z;
    const int m0 = blockIdx.y * 64;
    const int n0 = blockIdx.x * 64;
    __shared__ float Ws[16][68];
    __shared__ float Xs[16][68];
    const int t = threadIdx.x, tx = t & 15, ty = t >> 4;
    float acc[4][4] = {};
    const float* aob = g_ao + (size_t)b * HEADS * N_TOK * DHEAD;

    for (int kk = 0; kk < 128; kk += 16) {
#pragma unroll
        for (int r = 0; r < 4; r++) {
            int idx = r * 256 + t;
            int m = idx >> 4, k = idx & 15;
            Ws[k][m] = w[(m0 + m) * 128 + kk + k];
            int n = idx >> 4, kq = idx & 15;
            int c = kk + kq;
            Xs[kq][n] = aob[((c >> 5) * N_TOK + n0 + n) * DHEAD + (c & 31)];
        }
        __syncthreads();
#pragma unroll
        for (int k = 0; k < 16; k++) {
            float4 w4 = *(const float4*)&Ws[k][ty * 4];
            float4 x4 = *(const float4*)&Xs[k][tx * 4];
            float wa[4] = {w4.x, w4.y, w4.z, w4.w};
            float xa[4] = {x4.x, x4.y, x4.z, x4.w};
#pragma unroll
            for (int mi = 0; mi < 4; mi++)
#pragma unroll
                for (int ni = 0; ni < 4; ni++)
                    acc[mi][ni] = fmaf(wa[mi], xa[ni], acc[mi][ni]);
        }
        __syncthreads();
    }

#pragma unroll
    for (int mi = 0; mi < 4; mi++) {
        const int o = m0 + ty * 4 + mi;
        const float bv = bias[o];
        float4 v = make_float4(acc[mi][0] + bv, acc[mi][1] + bv,
                               acc[mi][2] + bv, acc[mi][3] + bv);
        *(float4*)&y[((size_t)b * CDIM + o) * N_TOK + n0 + tx * 4] = v;
    }
}

// ---------------------------------------------------------------------------
extern "C" void kernel_launch(void* const* d_in, const int* in_sizes, int n_in,
                              void* d_out, int out_size) {
    const float* x     = (const float*)d_in[0];   // [2,256,64,64]
    const float* w_qkv = (const float*)d_in[1];   // [384,256]
    const float* w_out = (const float*)d_in[2];   // [256,128]
    const float* b_out = (const float*)d_in[3];   // [256]
    float* y = (float*)d_out;                     // [2,256,64,64]

    qkv_kernel<<<dim3(64, 6, 2), 256>>>(x, w_qkv);
    attn_kernel<<<dim3(64, 4, 2), 256>>>();
    proj_kernel<<<dim3(64, 4, 2), 256>>>(w_out, b_out, y);
}

// round 15
// speedup vs baseline: 1.0120x; 1.0120x over previous
#include <cuda_runtime.h>

#define N_TOK  4096
#define HEADS  4
#define DHEAD  32
#define BATCH  2
#define CDIM   256
#define SCALE  0.17677669529663687f   // 1/sqrt(32)

// Scratch (device globals -- no allocations allowed)
__device__ float g_q [BATCH*HEADS*DHEAD*N_TOK];   // [b][h][d][n]
__device__ float g_k [BATCH*HEADS*DHEAD*N_TOK];   // [b][h][d][n]
__device__ float g_v [BATCH*HEADS*N_TOK*DHEAD];   // [b][h][n][d]
__device__ float g_ao[BATCH*HEADS*N_TOK*DHEAD];   // [b][h][n][d]

// ---- packed f32x2 helpers (Blackwell FFMA2 path, PTX-only) ------------------
typedef unsigned long long u64;

__device__ __forceinline__ u64 bcast2(float x) {
    u64 r; asm("mov.b64 %0, {%1, %1};" : "=l"(r) : "f"(x)); return r;
}
__device__ __forceinline__ u64 pack2(float lo, float hi) {
    u64 r; asm("mov.b64 %0, {%1, %2};" : "=l"(r) : "f"(lo), "f"(hi)); return r;
}
__device__ __forceinline__ void unpack2(u64 v, float& lo, float& hi) {
    asm("mov.b64 {%0, %1}, %2;" : "=f"(lo), "=f"(hi) : "l"(v));
}
__device__ __forceinline__ u64 ffma2(u64 a, u64 b, u64 c) {
    u64 d; asm("fma.rn.f32x2 %0, %1, %2, %3;" : "=l"(d) : "l"(a), "l"(b), "l"(c));
    return d;
}
__device__ __forceinline__ u64 fmul2(u64 a, u64 b) {
    u64 d; asm("mul.rn.f32x2 %0, %1, %2;" : "=l"(d) : "l"(a), "l"(b));
    return d;
}
__device__ __forceinline__ u64 ld2(const float* p) {   // 64-bit packed shared/global load
    return *(const u64*)p;
}

// ---------------------------------------------------------------------------
// Kernel 1: QKV projection.  C[o][i] = sum_c W[o][c] * X[c][i]
// M=384 (o), N=4096 (i), K=256, per batch. 64x64 tile, 4x4 micro, 256 thr.
// Inner product in f32x2: acc pairs packed along n.
// ---------------------------------------------------------------------------
__global__ __launch_bounds__(256) void qkv_kernel(const float* __restrict__ x,
                                                  const float* __restrict__ w) {
    const int b  = blockIdx.z;
    const int m0 = blockIdx.y * 64;
    const int n0 = blockIdx.x * 64;
    __shared__ float Ws[16][68];
    __shared__ float Xs[16][68];
    const int t = threadIdx.x, tx = t & 15, ty = t >> 4;
    u64 acc[4][2] = {};
    const float* xb = x + (size_t)b * CDIM * N_TOK;

    for (int kk = 0; kk < CDIM; kk += 16) {
#pragma unroll
        for (int r = 0; r < 4; r++) {
            int idx = r * 256 + t;
            int m = idx >> 4, k = idx & 15;
            Ws[k][m] = w[(m0 + m) * CDIM + kk + k];
            int k2 = idx >> 6, n = idx & 63;
            Xs[k2][n] = xb[(kk + k2) * N_TOK + n0 + n];
        }
        __syncthreads();
#pragma unroll
        for (int k = 0; k < 16; k++) {
            float4 w4 = *(const float4*)&Ws[k][ty * 4];
            u64 xp0 = ld2(&Xs[k][tx * 4]);
            u64 xp1 = ld2(&Xs[k][tx * 4 + 2]);
            float wa[4] = {w4.x, w4.y, w4.z, w4.w};
#pragma unroll
            for (int mi = 0; mi < 4; mi++) {
                u64 wb = bcast2(wa[mi]);
                acc[mi][0] = ffma2(wb, xp0, acc[mi][0]);
                acc[mi][1] = ffma2(wb, xp1, acc[mi][1]);
            }
        }
        __syncthreads();
    }

#pragma unroll
    for (int mi = 0; mi < 4; mi++) {
        const int o  = m0 + ty * 4 + mi;
        const int g  = o >> 7;          // 0=q 1=k 2=v
        const int r7 = o & 127;
        const int h  = r7 >> 5, d = r7 & 31;
        const int n  = n0 + tx * 4;
        if (g == 0) {
            u64 sb = bcast2(SCALE);
            u64 q0 = fmul2(acc[mi][0], sb), q1 = fmul2(acc[mi][1], sb);
            u64* dst = (u64*)&g_q[(((b * HEADS + h) * DHEAD + d) * N_TOK) + n];
            dst[0] = q0; dst[1] = q1;
        } else if (g == 1) {
            u64* dst = (u64*)&g_k[(((b * HEADS + h) * DHEAD + d) * N_TOK) + n];
            dst[0] = acc[mi][0]; dst[1] = acc[mi][1];
        } else {
            float a0, a1, a2, a3;
            unpack2(acc[mi][0], a0, a1);
            unpack2(acc[mi][1], a2, a3);
            float av[4] = {a0, a1, a2, a3};
#pragma unroll
            for (int ni = 0; ni < 4; ni++)
                g_v[(((b * HEADS + h) * N_TOK) + n + ni) * DHEAD + d] = av[ni];
        }
    }
}

// ---------------------------------------------------------------------------
// Kernel 2: flash attention, fp32, online softmax, f32x2 GEMM cores.
// ---------------------------------------------------------------------------
__global__ __launch_bounds__(256) void attn_kernel() {
    const int b = blockIdx.z, h = blockIdx.y, it = blockIdx.x;
    const int bh = b * HEADS + h;
    const float* qb = g_q + (size_t)bh * DHEAD * N_TOK;
    const float* kb = g_k + (size_t)bh * DHEAD * N_TOK;
    const float* vb = g_v + (size_t)bh * N_TOK * DHEAD;
    float* aob = g_ao + (size_t)bh * N_TOK * DHEAD;
    const int i0 = it * 64;

    __shared__ float QsT[32][68];
    __shared__ float KsT[32][68];
    __shared__ float Vs [64][36];
    __shared__ float Ps [64][68];
    __shared__ float m_s[64], l_s[64], scale_s[64];

    const int t  = threadIdx.x;
    const int tx = t & 15, ty = t >> 4;     // S mapping
    const int d4 = t & 7,  irow = t >> 3;   // PV mapping

    // Load Q tile ([d][n] layout)
#pragma unroll
    for (int r = 0; r < 2; r++) {
        int idx = r * 256 + t;
        int d = idx >> 4, c = idx & 15;
        *(float4*)&QsT[d][c * 4] = *(const float4*)&qb[d * N_TOK + i0 + c * 4];
    }
    if (t < 64) { m_s[t] = -1e30f; l_s[t] = 0.f; }

    u64 o0[2] = {}, o1[2] = {};   // O accum pairs over d; rows irow*2, irow*2+1

    for (int jt = 0; jt < 64; jt++) {
        const int j0 = jt * 64;
#pragma unroll
        for (int r = 0; r < 2; r++) {
            int idx = r * 256 + t;
            int d = idx >> 4, c = idx & 15;
            *(float4*)&KsT[d][c * 4] = *(const float4*)&kb[d * N_TOK + j0 + c * 4];
            int j = idx >> 3, c2 = idx & 7;
            *(float4*)&Vs[j][c2 * 4] = *(const float4*)&vb[(j0 + j) * DHEAD + c2 * 4];
        }
        __syncthreads();

        // S = Q K^T  (64x64, each thread 4 rows x 2 packed col-pairs)
        u64 acc[4][2] = {};
#pragma unroll
        for (int d = 0; d < 32; d++) {
            float4 q4 = *(const float4*)&QsT[d][ty * 4];
            u64 kp0 = ld2(&KsT[d][tx * 4]);
            u64 kp1 = ld2(&KsT[d][tx * 4 + 2]);
            float qa[4] = {q4.x, q4.y, q4.z, q4.w};
#pragma unroll
            for (int mi = 0; mi < 4; mi++) {
                u64 qbd = bcast2(qa[mi]);
                acc[mi][0] = ffma2(qbd, kp0, acc[mi][0]);
                acc[mi][1] = ffma2(qbd, kp1, acc[mi][1]);
            }
        }

        // Online softmax per row
#pragma unroll
        for (int mi = 0; mi < 4; mi++) {
            const int i = ty * 4 + mi;
            float s0, s1, s2, s3;
            unpack2(acc[mi][0], s0, s1);
            unpack2(acc[mi][1], s2, s3);
            float rmax = fmaxf(fmaxf(s0, s1), fmaxf(s2, s3));
#pragma unroll
            for (int msk = 8; msk >= 1; msk >>= 1)
                rmax = fmaxf(rmax, __shfl_xor_sync(0xffffffffu, rmax, msk));
            const float mold = m_s[i];
            const float mnew = fmaxf(mold, rmax);
            float p0 = __expf(s0 - mnew);
            float p1 = __expf(s1 - mnew);
            float p2 = __expf(s2 - mnew);
            float p3 = __expf(s3 - mnew);
            float rsum = (p0 + p1) + (p2 + p3);
#pragma unroll
            for (int msk = 8; msk >= 1; msk >>= 1)
                rsum += __shfl_xor_sync(0xffffffffu, rsum, msk);
            *(float4*)&Ps[i][tx * 4] = make_float4(p0, p1, p2, p3);
            if (tx == 0) {
                const float sc = __expf(mold - mnew);
                m_s[i] = mnew;
                scale_s[i] = sc;
                l_s[i] = l_s[i] * sc + rsum;
            }
        }
        __syncthreads();

        // O = O*scale + P @ V   (f32x2 over d pairs)
        {
            u64 sb0 = bcast2(scale_s[irow * 2]);
            u64 sb1 = bcast2(scale_s[irow * 2 + 1]);
            o0[0] = fmul2(o0[0], sb0); o0[1] = fmul2(o0[1], sb0);
            o1[0] = fmul2(o1[0], sb1); o1[1] = fmul2(o1[1], sb1);
        }
#pragma unroll
        for (int j = 0; j < 64; j++) {
            u64 vp0 = ld2(&Vs[j][d4 * 4]);
            u64 vp1 = ld2(&Vs[j][d4 * 4 + 2]);
            u64 pb0 = bcast2(Ps[irow * 2][j]);
            u64 pb1 = bcast2(Ps[irow * 2 + 1][j]);
            o0[0] = ffma2(pb0, vp0, o0[0]);
            o0[1] = ffma2(pb0, vp1, o0[1]);
            o1[0] = ffma2(pb1, vp0, o1[0]);
            o1[1] = ffma2(pb1, vp1, o1[1]);
        }
        __syncthreads();
    }

    {
        u64 ib0 = bcast2(1.0f / l_s[irow * 2]);
        u64 ib1 = bcast2(1.0f / l_s[irow * 2 + 1]);
        u64* dst0 = (u64*)&aob[(i0 + irow * 2)     * DHEAD + d4 * 4];
        u64* dst1 = (u64*)&aob[(i0 + irow * 2 + 1) * DHEAD + d4 * 4];
        dst0[0] = fmul2(o0[0], ib0); dst0[1] = fmul2(o0[1], ib0);
        dst1[0] = fmul2(o1[0], ib1); dst1[1] = fmul2(o1[1], ib1);
    }
}

// ---------------------------------------------------------------------------
// Kernel 3: output projection.  y[o][i] = bias[o] + sum_c w[o][c] * ao(c,i)
// ---------------------------------------------------------------------------
__global__ __launch_bounds__(256) void proj_kernel(const float* __restrict__ w,
                                                   const float* __restrict__ bias,
                                                   float* __restrict__ y) {
    const int b  = blockIdx.z;
    const int m0 = blockIdx.y * 64;
    const int n0 = blockIdx.x * 64;
    __shared__ float Ws[16][68];
    __shared__ float Xs[16][68];
    const int t = threadIdx.x, tx = t & 15, ty = t >> 4;
    u64 acc[4][2] = {};
    const float* aob = g_ao + (size_t)b * HEADS * N_TOK * DHEAD;

    for (int kk = 0; kk < 128; kk += 16) {
#pragma unroll
        for (int r = 0; r < 4; r++) {
            int idx = r * 256 + t;
            int m = idx >> 4, k = idx & 15;
            Ws[k][m] = w[(m0 + m) * 128 + kk + k];
            int n = idx >> 4, kq = idx & 15;
            int c = kk + kq;
            Xs[kq][n] = aob[((c >> 5) * N_TOK + n0 + n) * DHEAD + (c & 31)];
        }
        __syncthreads();
#pragma unroll
        for (int k = 0; k < 16; k++) {
            float4 w4 = *(const float4*)&Ws[k][ty * 4];
            u64 xp0 = ld2(&Xs[k][tx * 4]);
            u64 xp1 = ld2(&Xs[k][tx * 4 + 2]);
            float wa[4] = {w4.x, w4.y, w4.z, w4.w};
#pragma unroll
            for (int mi = 0; mi < 4; mi++) {
                u64 wb = bcast2(wa[mi]);
                acc[mi][0] = ffma2(wb, xp0, acc[mi][0]);
                acc[mi][1] = ffma2(wb, xp1, acc[mi][1]);
            }
        }
        __syncthreads();
    }

#pragma unroll
    for (int mi = 0; mi < 4; mi++) {
        const int o = m0 + ty * 4 + mi;
        float a0, a1, a2, a3;
        unpack2(acc[mi][0], a0, a1);
        unpack2(acc[mi][1], a2, a3);
        const float bv = bias[o];
        float4 v = make_float4(a0 + bv, a1 + bv, a2 + bv, a3 + bv);
        *(float4*)&y[((size_t)b * CDIM + o) * N_TOK + n0 + tx * 4] = v;
    }
}

// ---------------------------------------------------------------------------
extern "C" void kernel_launch(void* const* d_in, const int* in_sizes, int n_in,
                              void* d_out, int out_size) {
    const float* x     = (const float*)d_in[0];   // [2,256,64,64]
    const float* w_qkv = (const float*)d_in[1];   // [384,256]
    const float* w_out = (const float*)d_in[2];   // [256,128]
    const float* b_out = (const float*)d_in[3];   // [256]
    float* y = (float*)d_out;                     // [2,256,64,64]

    qkv_kernel<<<dim3(64, 6, 2), 256>>>(x, w_qkv);
    attn_kernel<<<dim3(64, 4, 2), 256>>>();
    proj_kernel<<<dim3(64, 4, 2), 256>>>(w_out, b_out, y);
}